// round 10
// baseline (speedup 1.0000x reference)
#include <cuda_runtime.h>
#include <cstdint>

// Problem constants (fixed by reference)
#define RDIM 4096
#define TLEN 2048
#define IDIM 8
#define ODIM 8
#define NBLK 128                 // persistent CTAs, co-resident on 148 SMs
#define NTHR 512                 // 16 warps
#define NSLOT (RDIM / 2)         // 2048 warp-slots (2 rows each, 16 lanes/row)
#define SLOTS_PER_CTA 16
#define MAXC 768                 // stage-1 compaction capacity (nnz ~410 +-20)
#define NSUB_MAX 36              // entries per lane: 16*36=576 nnz/row cap (+8.7 sd)
#define NE NSUB_MAX              // register-resident entries per lane
#define CLUSTER_SIZE 2
#define H_BYTES (RDIM * 4)       // 16 KB
#define SLICE_BYTES (H_BYTES / CLUSTER_SIZE)

struct __align__(8) Ent { float v; int c; };

// Scratch (device globals: no allocation allowed)
__device__ __align__(16) Ent g_ellp[NSLOT * NSUB_MAX * 32];  // ~19 MB packed ELL
__device__ Ent      g_rcomp[RDIM * MAXC];                    // stage-1 compaction
__device__ int      g_np[NSLOT];                             // sub-iters per slot
__device__ float    g_u[TLEN * RDIM];                        // Win @ x_t (32 MB)
__device__ __align__(16) float g_hall[(TLEN + 1) * RDIM];    // all hidden states
__device__ unsigned g_arr[NBLK];                             // barrier cells

// STRONG scoped sync (guaranteed visibility; relaxed = no fence)
__device__ __forceinline__ unsigned ld_rlx(const unsigned* p) {
    unsigned v;
    asm volatile("ld.relaxed.gpu.global.u32 %0, [%1];" : "=r"(v) : "l"(p) : "memory");
    return v;
}
__device__ __forceinline__ void red_rel_add(unsigned* p) {
    asm volatile("red.release.gpu.global.add.u32 [%0], 1;" :: "l"(p) : "memory");
}
__device__ __forceinline__ uint32_t smem_u32(const void* p) {
    uint32_t a;
    asm("{ .reg .u64 t; cvta.to.shared.u64 t, %1; cvt.u32.u64 %0, t; }"
        : "=r"(a) : "l"(p));
    return a;
}
__device__ __forceinline__ float tanh_hw(float x) {
    float r;
    asm("tanh.approx.f32 %0, %1;" : "=f"(r) : "f"(x));
    return r;
}
__device__ __forceinline__ uint32_t ctarank() {
    uint32_t r;
    asm("mov.u32 %0, %%cluster_ctarank;" : "=r"(r));
    return r;
}
#define CLUSTER_SYNC() do { \
    asm volatile("barrier.cluster.arrive.aligned;" ::: "memory"); \
    asm volatile("barrier.cluster.wait.aligned;" ::: "memory"); \
} while (0)

// ---------------------------------------------------------------------------
// K1: u[t][r] = sum_i Win[r,i] * x[t,i]
// ---------------------------------------------------------------------------
__global__ void k_u(const float* __restrict__ x, const float* __restrict__ Win) {
    int t = blockIdx.x;
    __shared__ float xs[IDIM];
    if (threadIdx.x < IDIM) xs[threadIdx.x] = x[t * IDIM + threadIdx.x];
    __syncthreads();
    for (int r = threadIdx.x; r < RDIM; r += blockDim.x) {
        const float4* w = (const float4*)(Win + r * IDIM);
        float4 a = __ldg(&w[0]), b = __ldg(&w[1]);
        g_u[t * RDIM + r] = a.x * xs[0] + a.y * xs[1] + a.z * xs[2] + a.w * xs[3]
                          + b.x * xs[4] + b.y * xs[5] + b.z * xs[6] + b.w * xs[7];
    }
}

// ---------------------------------------------------------------------------
// K2: per slot (one warp): compact 2 rows of W (zeros exact), then lane 0
// greedily assigns each entry a (sub-iter, lane) such that all 32 lanes of a
// sub-iter hit distinct smem banks. Lanes 0-15: row 2s; lanes 16-31: row 2s+1.
// ---------------------------------------------------------------------------
__global__ void k_prep(const float* __restrict__ W) {
    int wid  = threadIdx.x >> 5;
    int lane = threadIdx.x & 31;
    int slot = blockIdx.x * (blockDim.x / 32) + wid;
    if (slot >= NSLOT) return;

    Ent* ell = g_ellp + (size_t)slot * (NSUB_MAX * 32);

    // prefill padding: v=0, col=lane (conflict-free dummies)
    for (int idx = lane; idx < NSUB_MAX * 32; idx += 32)
        ell[idx] = Ent{0.0f, idx & 31};

    int cnts[2];
    for (int half = 0; half < 2; half++) {
        int row = 2 * slot + half;
        const float* wr = W + (size_t)row * RDIM;
        Ent* dst = g_rcomp + (size_t)row * MAXC;
        int cnt = 0;
        for (int c0 = 0; c0 < RDIM; c0 += 32) {
            float v = wr[c0 + lane];
            unsigned bal = __ballot_sync(0xffffffffu, v != 0.0f);
            if (v != 0.0f) {
                int pos = cnt + __popc(bal & ((1u << lane) - 1u));
                if (pos < MAXC) dst[pos] = Ent{v, c0 + lane};
            }
            cnt += __popc(bal);
        }
        cnts[half] = cnt < MAXC ? cnt : MAXC;
    }
    __syncwarp();

    __shared__ int s_mask[8][NSUB_MAX];
    __shared__ int s_cnt[8][2][NSUB_MAX];
    if (lane == 0) {
        int kmax = 0;
        for (int k = 0; k < NSUB_MAX; k++) {
            s_mask[wid][k] = 0;
            s_cnt[wid][0][k] = 0;
            s_cnt[wid][1][k] = 0;
        }
        for (int half = 0; half < 2; half++) {
            int row = 2 * slot + half;
            const Ent* src = g_rcomp + (size_t)row * MAXC;
            int base = 0;
            for (int i = 0; i < cnts[half]; i++) {
                Ent e = src[i];
                int b = e.c & 31;
                while (base < NSUB_MAX && s_cnt[wid][half][base] >= 16) base++;
                if (base >= NSUB_MAX) break;          // statistically never
                int k = -1;
                for (int kk = base; kk < NSUB_MAX; kk++) {
                    if (s_cnt[wid][half][kk] < 16 && !((s_mask[wid][kk] >> b) & 1)) {
                        k = kk; break;
                    }
                }
                if (k < 0) k = base;                   // accept rare conflict
                int j = s_cnt[wid][half][k];
                s_cnt[wid][half][k] = j + 1;
                s_mask[wid][k] |= 1 << b;
                if (k > kmax) kmax = k;
                ell[k * 32 + half * 16 + j] = e;
            }
        }
        g_np[slot] = kmax + 1;
    }
}

// ---------------------------------------------------------------------------
// K3: per-replay init
// ---------------------------------------------------------------------------
__global__ void k_init() {
    int i = blockIdx.x * blockDim.x + threadIdx.x;
    if (i < RDIM) g_hall[i] = 0.0f;   // h_0 = 0
    if (i < NBLK) g_arr[i] = 0u;
}

// ---------------------------------------------------------------------------
// K4 (launch #4 -> ncu target): persistent recurrence, cluster (2,1,1).
//   - W entries REGISTER-resident (36 vals + 18 packed byte-offset regs/lane).
//   - h_{t-1} staged via cooperative-sliced MULTICAST TMA: each CTA of a pair
//     fetches 8 KB and multicasts to both -> per-line L2 reads halve (the
//     broadcast hotspot was ~500 cyc/step of serialized slice service).
//   - Barrier: ONE red.release per warp (lane 0 folds both rows), warp 0
//     polls ld.relaxed.gpu over 128 cells; target 16*t.
//   - expect_tx at step TAIL behind __syncthreads: peer multicast (triggered
//     by my releases; last is tid0's which follows tid0's expect) can never
//     outrun my mbar accounting.
// ---------------------------------------------------------------------------
__global__ void __launch_bounds__(NTHR, 1) __cluster_dims__(CLUSTER_SIZE, 1, 1)
k_main() {
    __shared__ __align__(16) float sh[RDIM];          // 16 KB h
    __shared__ __align__(8) unsigned long long mbar[1];

    const int tid  = threadIdx.x;
    const int wid  = tid >> 5;
    const int lane = tid & 31;
    const int slot = blockIdx.x * SLOTS_PER_CTA + wid;
    const uint32_t rank = ctarank();

    const uint32_t mbar_a = smem_u32(mbar);
    const uint32_t sh_a   = smem_u32(sh);

    if (tid == 0)
        asm volatile("mbarrier.init.shared.b64 [%0], 1;" :: "r"(mbar_a) : "memory");

    // one-time: load this lane's 36 entries into registers
    float    vv[NE];
    unsigned cp[NE / 2];   // two pre-scaled byte offsets per reg
    {
        const Ent* src = g_ellp + (size_t)slot * (NSUB_MAX * 32) + lane;
#pragma unroll
        for (int i = 0; i < NE; i += 2) {
            Ent e0 = src[i * 32];
            Ent e1 = src[(i + 1) * 32];
            vv[i]     = e0.v;
            vv[i + 1] = e1.v;
            cp[i >> 1] = ((unsigned)e0.c << 2) | ((unsigned)e1.c << 18);
        }
    }

    // lane 0 of each warp owns both rows (2*slot, 2*slot+1): float2 u prefetch
    float2 u2 = make_float2(0.f, 0.f);
    if (lane == 0) u2 = __ldg((const float2*)(g_u + 2 * slot));

    __syncthreads();                                   // mbar + reg load done
    if (tid == 0) {
        asm volatile("fence.proxy.async;" ::: "memory");
        asm volatile("mbarrier.arrive.expect_tx.shared.b64 _, [%0], %1;"
                     :: "r"(mbar_a), "r"((unsigned)H_BYTES) : "memory");
    }
    CLUSTER_SYNC();   // both CTAs' mbar init + expect_tx visible cluster-wide

    const char* shb = (const char*)sh;

    for (int t = 0; t < TLEN; ++t) {
        // ---- top-of-step: wait for all CTAs to have finished step t-1 ----
        if (tid < 32) {
            const unsigned tgt = 16u * (unsigned)t;
            if (tgt) {
                for (;;) {
                    unsigned m0 = ld_rlx(&g_arr[tid]);
                    unsigned m1 = ld_rlx(&g_arr[tid + 32]);
                    unsigned m2 = ld_rlx(&g_arr[tid + 64]);
                    unsigned m3 = ld_rlx(&g_arr[tid + 96]);
                    unsigned m  = min(min(m0, m1), min(m2, m3));
                    if (!__any_sync(0xffffffffu, m < tgt)) break;
                }
            }
            if (tid == 0) {
                // cooperative slice: fetch my half, multicast to both CTAs
                const float* src = g_hall + (size_t)t * RDIM + rank * (RDIM / 2);
                asm volatile(
                    "cp.async.bulk.shared::cluster.global"
                    ".mbarrier::complete_tx::bytes.multicast::cluster "
                    "[%0], [%1], %2, [%3], %4;"
                    :: "r"(sh_a + rank * SLICE_BYTES), "l"(src),
                       "r"((unsigned)SLICE_BYTES), "r"(mbar_a),
                       "h"((unsigned short)0x3)
                    : "memory");
            }
        }
        // all threads wait for both 8 KB slices (phase parity = t&1)
        {
            const unsigned par = (unsigned)(t & 1);
            unsigned done;
            asm volatile(
                "{\n\t.reg .pred p;\n\t"
                "mbarrier.try_wait.parity.acquire.cta.shared::cta.b64 p, [%1], %2;\n\t"
                "selp.b32 %0, 1, 0, p;\n\t}"
                : "=r"(done) : "r"(mbar_a), "r"(par) : "memory");
            if (!done) {
                asm volatile(
                    "{\n\t.reg .pred P1;\n\t"
                    "W%=:\n\t"
                    "mbarrier.try_wait.parity.acquire.cta.shared::cta.b64 P1, [%0], %1, 0x989680;\n\t"
                    "@P1 bra.uni D%=;\n\t"
                    "bra.uni W%=;\n\t"
                    "D%=:\n\t}"
                    :: "r"(mbar_a), "r"(par) : "memory");
            }
        }

        // ---- sparse dot: values/offsets from registers, gathers from smem ----
        float a0 = 0.0f, a1 = 0.0f;
#pragma unroll
        for (int i = 0; i < NE; i += 2) {
            unsigned p = cp[i >> 1];
            a0 += vv[i]     * *(const float*)(shb + (p & 0xFFFFu));
            a1 += vv[i + 1] * *(const float*)(shb + (p >> 16));
        }
        float acc = a0 + a1;
#pragma unroll
        for (int off = 8; off; off >>= 1)
            acc += __shfl_xor_sync(0xffffffffu, acc, off);
        // lanes 0-15 hold row 2s sum; lanes 16-31 hold row 2s+1 sum
        float accB = __shfl_sync(0xffffffffu, acc, 16);

        if (lane == 0) {
            float2 hv;
            hv.x = tanh_hw(acc  + u2.x);
            hv.y = tanh_hw(accB + u2.y);
            __stcg((float2*)(g_hall + (size_t)(t + 1) * RDIM + 2 * slot), hv);
            if (t + 1 < TLEN)
                u2 = __ldcg((const float2*)(g_u + (size_t)(t + 1) * RDIM + 2 * slot));
        }
        __syncthreads();   // all stores + all gather reads done CTA-wide

        if (tid == 0 && t + 1 < TLEN) {
            asm volatile("fence.proxy.async;" ::: "memory");
            asm volatile("mbarrier.arrive.expect_tx.shared.b64 _, [%0], %1;"
                         :: "r"(mbar_a), "r"((unsigned)H_BYTES) : "memory");
        }
        // arrive: one release per warp; tid0's release follows its expect_tx,
        // and peers fire only after seeing ALL 16 releases of this CTA.
        if (lane == 0) red_rel_add(&g_arr[blockIdx.x]);
    }

    CLUSTER_SYNC();   // keep smem alive for any in-flight peer multicast
}

// ---------------------------------------------------------------------------
// K5: out[t][o] = bias[o] + sum_r h_{t+1}[r] * Wout[o][r]
// ---------------------------------------------------------------------------
__global__ void k_out(const float* __restrict__ Wout, const float* __restrict__ bias,
                      float* __restrict__ out) {
    int t = blockIdx.x;
    const float4* h4 = (const float4*)(g_hall + (size_t)(t + 1) * RDIM);
    float acc[ODIM];
#pragma unroll
    for (int o = 0; o < ODIM; o++) acc[o] = 0.0f;

    for (int r4 = threadIdx.x; r4 < RDIM / 4; r4 += blockDim.x) {
        float4 h = h4[r4];
#pragma unroll
        for (int o = 0; o < ODIM; o++) {
            float4 w = __ldg((const float4*)(Wout + o * RDIM) + r4);
            acc[o] += h.x * w.x + h.y * w.y + h.z * w.z + h.w * w.w;
        }
    }
    __shared__ float red[8][ODIM];
    int wid = threadIdx.x >> 5, lane = threadIdx.x & 31;
#pragma unroll
    for (int o = 0; o < ODIM; o++) {
        float v = acc[o];
#pragma unroll
        for (int off = 16; off; off >>= 1)
            v += __shfl_xor_sync(0xffffffffu, v, off);
        if (lane == 0) red[wid][o] = v;
    }
    __syncthreads();
    if (threadIdx.x < ODIM) {
        float s = bias[threadIdx.x];
#pragma unroll
        for (int w = 0; w < 8; w++) s += red[w][threadIdx.x];
        out[t * ODIM + threadIdx.x] = s;
    }
}

// ---------------------------------------------------------------------------
extern "C" void kernel_launch(void* const* d_in, const int* in_sizes, int n_in,
                              void* d_out, int out_size) {
    (void)in_sizes; (void)n_in; (void)out_size;
    const float* x      = (const float*)d_in[0];  // [1, 2048, 8]
    const float* Win    = (const float*)d_in[1];  // [4096, 8]
    const float* W      = (const float*)d_in[2];  // [4096, 4096]
    const float* Wout_w = (const float*)d_in[3];  // [8, 4096]
    const float* Wout_b = (const float*)d_in[4];  // [8]
    float* out = (float*)d_out;                   // [1, 2048, 8]

    k_u<<<TLEN, 256>>>(x, Win);                   // launch 1
    k_prep<<<NSLOT / 8, 256>>>(W);                // launch 2
    k_init<<<(RDIM + 255) / 256, 256>>>();        // launch 3
    k_main<<<NBLK, NTHR>>>();                     // launch 4 <- ncu target
    k_out<<<TLEN, 256>>>(Wout_w, Wout_b, out);    // launch 5
}

// round 11
// speedup vs baseline: 1.2275x; 1.2275x over previous
#include <cuda_runtime.h>
#include <cstdint>

// Problem constants (fixed by reference)
#define RDIM 4096
#define TLEN 2048
#define IDIM 8
#define ODIM 8
#define NBLK 128                 // persistent CTAs, co-resident on 148 SMs
#define NTHR 512                 // 16 warps
#define NSLOT (RDIM / 2)         // 2048 warp-slots (2 rows each, 16 lanes/row)
#define SLOTS_PER_CTA 16
#define MAXC 768                 // stage-1 compaction capacity (nnz ~410 +-20)
#define NSUB_MAX 36              // entries per lane: 16*36=576 nnz/row cap (+8.7 sd)
#define NE NSUB_MAX              // register-resident entries per lane
#define H_BYTES (RDIM * 4)       // 16 KB
#define NGRP 4                   // CTA groups / h chunks
#define GRP_CTAS (NBLK / NGRP)   // 32 CTAs per group
#define CHUNK_BYTES (H_BYTES / NGRP)   // 4 KB
#define CHUNK_FLOATS (RDIM / NGRP)     // 1024

struct __align__(8) Ent { float v; int c; };

// Scratch (device globals: no allocation allowed)
__device__ __align__(16) Ent g_ellp[NSLOT * NSUB_MAX * 32];  // ~19 MB packed ELL
__device__ Ent      g_rcomp[RDIM * MAXC];                    // stage-1 compaction
__device__ int      g_np[NSLOT];                             // sub-iters per slot
__device__ float    g_u[TLEN * RDIM];                        // Win @ x_t (32 MB)
__device__ __align__(16) float g_hall[(TLEN + 1) * RDIM];    // all hidden states
__device__ unsigned g_arr[NBLK];                             // barrier cells

// STRONG scoped sync (guaranteed visibility; relaxed = no fence)
__device__ __forceinline__ unsigned ld_rlx(const unsigned* p) {
    unsigned v;
    asm volatile("ld.relaxed.gpu.global.u32 %0, [%1];" : "=r"(v) : "l"(p) : "memory");
    return v;
}
__device__ __forceinline__ void red_rel_add(unsigned* p) {
    asm volatile("red.release.gpu.global.add.u32 [%0], 1;" :: "l"(p) : "memory");
}
__device__ __forceinline__ uint32_t smem_u32(const void* p) {
    uint32_t a;
    asm("{ .reg .u64 t; cvta.to.shared.u64 t, %1; cvt.u32.u64 %0, t; }"
        : "=r"(a) : "l"(p));
    return a;
}
__device__ __forceinline__ float tanh_hw(float x) {
    float r;
    asm("tanh.approx.f32 %0, %1;" : "=f"(r) : "f"(x));
    return r;
}

// ---------------------------------------------------------------------------
// K1: u[t][r] = sum_i Win[r,i] * x[t,i]
// ---------------------------------------------------------------------------
__global__ void k_u(const float* __restrict__ x, const float* __restrict__ Win) {
    int t = blockIdx.x;
    __shared__ float xs[IDIM];
    if (threadIdx.x < IDIM) xs[threadIdx.x] = x[t * IDIM + threadIdx.x];
    __syncthreads();
    for (int r = threadIdx.x; r < RDIM; r += blockDim.x) {
        const float4* w = (const float4*)(Win + r * IDIM);
        float4 a = __ldg(&w[0]), b = __ldg(&w[1]);
        g_u[t * RDIM + r] = a.x * xs[0] + a.y * xs[1] + a.z * xs[2] + a.w * xs[3]
                          + b.x * xs[4] + b.y * xs[5] + b.z * xs[6] + b.w * xs[7];
    }
}

// ---------------------------------------------------------------------------
// K2: per slot (one warp): compact 2 rows of W (zeros exact), then lane 0
// greedily assigns each entry a (sub-iter, lane) such that all 32 lanes of a
// sub-iter hit distinct smem banks. Lanes 0-15: row 2s; lanes 16-31: row 2s+1.
// ---------------------------------------------------------------------------
__global__ void k_prep(const float* __restrict__ W) {
    int wid  = threadIdx.x >> 5;
    int lane = threadIdx.x & 31;
    int slot = blockIdx.x * (blockDim.x / 32) + wid;
    if (slot >= NSLOT) return;

    Ent* ell = g_ellp + (size_t)slot * (NSUB_MAX * 32);

    // prefill padding: v=0, col=lane (conflict-free dummies)
    for (int idx = lane; idx < NSUB_MAX * 32; idx += 32)
        ell[idx] = Ent{0.0f, idx & 31};

    int cnts[2];
    for (int half = 0; half < 2; half++) {
        int row = 2 * slot + half;
        const float* wr = W + (size_t)row * RDIM;
        Ent* dst = g_rcomp + (size_t)row * MAXC;
        int cnt = 0;
        for (int c0 = 0; c0 < RDIM; c0 += 32) {
            float v = wr[c0 + lane];
            unsigned bal = __ballot_sync(0xffffffffu, v != 0.0f);
            if (v != 0.0f) {
                int pos = cnt + __popc(bal & ((1u << lane) - 1u));
                if (pos < MAXC) dst[pos] = Ent{v, c0 + lane};
            }
            cnt += __popc(bal);
        }
        cnts[half] = cnt < MAXC ? cnt : MAXC;
    }
    __syncwarp();

    __shared__ int s_mask[8][NSUB_MAX];
    __shared__ int s_cnt[8][2][NSUB_MAX];
    if (lane == 0) {
        int kmax = 0;
        for (int k = 0; k < NSUB_MAX; k++) {
            s_mask[wid][k] = 0;
            s_cnt[wid][0][k] = 0;
            s_cnt[wid][1][k] = 0;
        }
        for (int half = 0; half < 2; half++) {
            int row = 2 * slot + half;
            const Ent* src = g_rcomp + (size_t)row * MAXC;
            int base = 0;
            for (int i = 0; i < cnts[half]; i++) {
                Ent e = src[i];
                int b = e.c & 31;
                while (base < NSUB_MAX && s_cnt[wid][half][base] >= 16) base++;
                if (base >= NSUB_MAX) break;          // statistically never
                int k = -1;
                for (int kk = base; kk < NSUB_MAX; kk++) {
                    if (s_cnt[wid][half][kk] < 16 && !((s_mask[wid][kk] >> b) & 1)) {
                        k = kk; break;
                    }
                }
                if (k < 0) k = base;                   // accept rare conflict
                int j = s_cnt[wid][half][k];
                s_cnt[wid][half][k] = j + 1;
                s_mask[wid][k] |= 1 << b;
                if (k > kmax) kmax = k;
                ell[k * 32 + half * 16 + j] = e;
            }
        }
        g_np[slot] = kmax + 1;
    }
}

// ---------------------------------------------------------------------------
// K3: per-replay init
// ---------------------------------------------------------------------------
__global__ void k_init() {
    int i = blockIdx.x * blockDim.x + threadIdx.x;
    if (i < RDIM) g_hall[i] = 0.0f;   // h_0 = 0
    if (i < NBLK) g_arr[i] = 0u;
}

// ---------------------------------------------------------------------------
// K4 (launch #4 -> ncu target): persistent recurrence.
//   - W entries REGISTER-resident (36 vals + 18 packed byte-offset regs/lane).
//   - h_{t-1} fetched in FOUR 4 KB chunks: warp w (w<4) polls CTA group w
//     (one cell per lane) and issues its chunk's cp.async.bulk as soon as
//     that group completes -> 12 KB of TMA hidden under arrival skew; the
//     post-last-arrival path is detect + 4 KB only.
//   - Barrier: heads red.release.gpu (covers own stcg); expect_tx(16 KB) at
//     step tail by tid0, then __syncthreads (also protects sh reuse).
// ---------------------------------------------------------------------------
__global__ void __launch_bounds__(NTHR, 1)
k_main() {
    __shared__ __align__(16) float sh[RDIM];          // 16 KB h
    __shared__ __align__(8) unsigned long long mbar[1];

    const int tid  = threadIdx.x;
    const int wid  = tid >> 5;
    const int lane = tid & 31;
    const int slot = blockIdx.x * SLOTS_PER_CTA + wid;
    const int half = lane >> 4;
    const int row  = 2 * slot + half;
    const bool head = (lane == 0) | (lane == 16);

    const uint32_t mbar_a = smem_u32(mbar);
    const uint32_t sh_a   = smem_u32(sh);

    if (tid == 0)
        asm volatile("mbarrier.init.shared.b64 [%0], 1;" :: "r"(mbar_a) : "memory");

    // one-time: load this lane's 36 entries into registers
    float    vv[NE];
    unsigned cp[NE / 2];   // two pre-scaled byte offsets per reg
    {
        const Ent* src = g_ellp + (size_t)slot * (NSUB_MAX * 32) + lane;
#pragma unroll
        for (int i = 0; i < NE; i += 2) {
            Ent e0 = src[i * 32];
            Ent e1 = src[(i + 1) * 32];
            vv[i]     = e0.v;
            vv[i + 1] = e1.v;
            cp[i >> 1] = ((unsigned)e0.c << 2) | ((unsigned)e1.c << 18);
        }
    }

    float u_next = head ? __ldg(&g_u[row]) : 0.0f;     // u for t=0
    __syncthreads();                                   // mbar init visible
    if (tid == 0) {
        asm volatile("fence.proxy.async;" ::: "memory");
        asm volatile("mbarrier.arrive.expect_tx.shared.b64 _, [%0], %1;"
                     :: "r"(mbar_a), "r"((unsigned)H_BYTES) : "memory");
    }
    __syncthreads();                                   // expect before any TMA

    const char* shb = (const char*)sh;

    for (int t = 0; t < TLEN; ++t) {
        // ---- warps 0-3: poll own CTA-group, then fetch its 4 KB chunk ----
        if (wid < NGRP) {
            if (t) {
                const unsigned tgt = 32u * (unsigned)t;
                const unsigned* cell = &g_arr[GRP_CTAS * wid + lane];
                for (;;) {
                    unsigned v = ld_rlx(cell);
                    if (!__any_sync(0xffffffffu, v < tgt)) break;
                }
            }
            if (lane == 0) {
                const float* src = g_hall + (size_t)t * RDIM + wid * CHUNK_FLOATS;
                asm volatile(
                    "cp.async.bulk.shared::cluster.global.mbarrier::complete_tx::bytes "
                    "[%0], [%1], %2, [%3];"
                    :: "r"(sh_a + wid * CHUNK_BYTES), "l"(src),
                       "r"((unsigned)CHUNK_BYTES), "r"(mbar_a)
                    : "memory");
            }
        }
        // all threads wait until all 4 chunks landed (phase parity = t&1)
        {
            const unsigned par = (unsigned)(t & 1);
            unsigned done;
            asm volatile(
                "{\n\t.reg .pred p;\n\t"
                "mbarrier.try_wait.parity.acquire.cta.shared::cta.b64 p, [%1], %2;\n\t"
                "selp.b32 %0, 1, 0, p;\n\t}"
                : "=r"(done) : "r"(mbar_a), "r"(par) : "memory");
            if (!done) {
                asm volatile(
                    "{\n\t.reg .pred P1;\n\t"
                    "W%=:\n\t"
                    "mbarrier.try_wait.parity.acquire.cta.shared::cta.b64 P1, [%0], %1, 0x989680;\n\t"
                    "@P1 bra.uni D%=;\n\t"
                    "bra.uni W%=;\n\t"
                    "D%=:\n\t}"
                    :: "r"(mbar_a), "r"(par) : "memory");
            }
        }

        // ---- sparse dot: values/offsets from registers, gathers from smem ----
        float a0 = 0.0f, a1 = 0.0f;
#pragma unroll
        for (int i = 0; i < NE; i += 2) {
            unsigned p = cp[i >> 1];
            a0 += vv[i]     * *(const float*)(shb + (p & 0xFFFFu));
            a1 += vv[i + 1] * *(const float*)(shb + (p >> 16));
        }
        float acc = a0 + a1;
#pragma unroll
        for (int off = 8; off; off >>= 1)
            acc += __shfl_xor_sync(0xffffffffu, acc, off);

        if (head) {
            float hv = tanh_hw(acc + u_next);          // HW MUFU.TANH
            __stcg(g_hall + (size_t)(t + 1) * RDIM + row, hv);
            // arrive: release covers own h store; strong -> guaranteed visible
            red_rel_add(&g_arr[blockIdx.x]);
            if (t + 1 < TLEN) u_next = __ldcg(&g_u[(size_t)(t + 1) * RDIM + row]);
        }
        // re-arm mbar for next step; must precede any warp's next-step TMA
        if (tid == 0 && t + 1 < TLEN) {
            asm volatile("fence.proxy.async;" ::: "memory");
            asm volatile("mbarrier.arrive.expect_tx.shared.b64 _, [%0], %1;"
                         :: "r"(mbar_a), "r"((unsigned)H_BYTES) : "memory");
        }
        // tail sync: (a) orders expect_tx before next TMAs, (b) protects sh
        // reuse (group-parallel polling no longer implies own-CTA completion)
        __syncthreads();
    }
}

// ---------------------------------------------------------------------------
// K5: out[t][o] = bias[o] + sum_r h_{t+1}[r] * Wout[o][r]
// ---------------------------------------------------------------------------
__global__ void k_out(const float* __restrict__ Wout, const float* __restrict__ bias,
                      float* __restrict__ out) {
    int t = blockIdx.x;
    const float4* h4 = (const float4*)(g_hall + (size_t)(t + 1) * RDIM);
    float acc[ODIM];
#pragma unroll
    for (int o = 0; o < ODIM; o++) acc[o] = 0.0f;

    for (int r4 = threadIdx.x; r4 < RDIM / 4; r4 += blockDim.x) {
        float4 h = h4[r4];
#pragma unroll
        for (int o = 0; o < ODIM; o++) {
            float4 w = __ldg((const float4*)(Wout + o * RDIM) + r4);
            acc[o] += h.x * w.x + h.y * w.y + h.z * w.z + h.w * w.w;
        }
    }
    __shared__ float red[8][ODIM];
    int wid = threadIdx.x >> 5, lane = threadIdx.x & 31;
#pragma unroll
    for (int o = 0; o < ODIM; o++) {
        float v = acc[o];
#pragma unroll
        for (int off = 16; off; off >>= 1)
            v += __shfl_xor_sync(0xffffffffu, v, off);
        if (lane == 0) red[wid][o] = v;
    }
    __syncthreads();
    if (threadIdx.x < ODIM) {
        float s = bias[threadIdx.x];
#pragma unroll
        for (int w = 0; w < 8; w++) s += red[w][threadIdx.x];
        out[t * ODIM + threadIdx.x] = s;
    }
}

// ---------------------------------------------------------------------------
extern "C" void kernel_launch(void* const* d_in, const int* in_sizes, int n_in,
                              void* d_out, int out_size) {
    (void)in_sizes; (void)n_in; (void)out_size;
    const float* x      = (const float*)d_in[0];  // [1, 2048, 8]
    const float* Win    = (const float*)d_in[1];  // [4096, 8]
    const float* W      = (const float*)d_in[2];  // [4096, 4096]
    const float* Wout_w = (const float*)d_in[3];  // [8, 4096]
    const float* Wout_b = (const float*)d_in[4];  // [8]
    float* out = (float*)d_out;                   // [1, 2048, 8]

    k_u<<<TLEN, 256>>>(x, Win);                   // launch 1
    k_prep<<<NSLOT / 8, 256>>>(W);                // launch 2
    k_init<<<(RDIM + 255) / 256, 256>>>();        // launch 3
    k_main<<<NBLK, NTHR>>>();                     // launch 4 <- ncu target
    k_out<<<TLEN, 256>>>(Wout_w, Wout_b, out);    // launch 5
}